// round 11
// baseline (speedup 1.0000x reference)
#include <cuda_runtime.h>
#include <cuda_bf16.h>
#include <cstdint>

// Model dims
#define Lc   4
#define Dc   2048
#define Hc   16
#define HDc  128
#define Ic   5632
#define Vc   32000
#define Bc   2
#define Sc   1024
#define Tc   (Bc*Sc)        // 2048 tokens
#define QKVc (3*Hc*HDc)     // 6144
#define GUc  (2*Ic)         // 11264

// ---------------- scratch (static device globals; no allocations) ----------
__device__ float g_h  [Tc*Dc];     // residual (fp32)
__device__ float g_qkv[Tc*QKVc];   // qkv fp32 (attention input; reused as final-norm x)
__device__ float g_gu [Tc*GUc];    // gate+up fp32

// split activations (bf16 hi/lo)
__device__ __nv_bfloat16 g_xh[Tc*Dc],  g_xl[Tc*Dc];
__device__ __nv_bfloat16 g_oh[Tc*Dc],  g_ol[Tc*Dc];
__device__ __nv_bfloat16 g_ah[Tc*Ic],  g_al[Tc*Ic];

// split weights (bf16 hi/lo)
__device__ __nv_bfloat16 g_wqkvh[Lc*QKVc*Dc], g_wqkvl[Lc*QKVc*Dc];
__device__ __nv_bfloat16 g_woh  [Lc*Dc*Dc],   g_wol  [Lc*Dc*Dc];
__device__ __nv_bfloat16 g_wguh [Lc*GUc*Dc],  g_wgul [Lc*GUc*Dc];
__device__ __nv_bfloat16 g_wdh  [Lc*Dc*Ic],   g_wdl  [Lc*Dc*Ic];

// ---------------- small helpers --------------------------------------------
__device__ __forceinline__ uint32_t smem_u32(const void* p) {
    uint32_t a;
    asm("{ .reg .u64 t; cvta.to.shared.u64 t, %1; cvt.u32.u64 %0, t; }"
        : "=r"(a) : "l"(p));
    return a;
}
__device__ __forceinline__ void split_store4(__nv_bfloat16* hp, __nv_bfloat16* lp,
                                             long long off, float4 v) {
    __nv_bfloat16 h0 = __float2bfloat16(v.x), h1 = __float2bfloat16(v.y);
    __nv_bfloat16 h2 = __float2bfloat16(v.z), h3 = __float2bfloat16(v.w);
    __nv_bfloat16 l0 = __float2bfloat16(v.x - __bfloat162float(h0));
    __nv_bfloat16 l1 = __float2bfloat16(v.y - __bfloat162float(h1));
    __nv_bfloat16 l2 = __float2bfloat16(v.z - __bfloat162float(h2));
    __nv_bfloat16 l3 = __float2bfloat16(v.w - __bfloat162float(h3));
    *(ushort4*)(hp + off) = make_ushort4(__bfloat16_as_ushort(h0), __bfloat16_as_ushort(h1),
                                         __bfloat16_as_ushort(h2), __bfloat16_as_ushort(h3));
    *(ushort4*)(lp + off) = make_ushort4(__bfloat16_as_ushort(l0), __bfloat16_as_ushort(l1),
                                         __bfloat16_as_ushort(l2), __bfloat16_as_ushort(l3));
}

// ---------------- weight split ---------------------------------------------
__global__ void split_kernel(const float* __restrict__ s,
                             __nv_bfloat16* __restrict__ hp,
                             __nv_bfloat16* __restrict__ lp, long long n) {
    long long i = ((long long)blockIdx.x * blockDim.x + threadIdx.x) * 4;
    if (i >= n) return;
    split_store4(hp, lp, i, *(const float4*)(s + i));
}

// ---------------- embedding gather -----------------------------------------
__global__ void embed_kernel(const int* __restrict__ ids,
                             const float* __restrict__ emb,
                             float* __restrict__ h) {
    const int t = blockIdx.x;
    const int id = ids[t];
    const float4* src = (const float4*)(emb + (long long)id * Dc);
    float4* dst = (float4*)(h + (long long)t * Dc);
    for (int i = threadIdx.x; i < Dc / 4; i += blockDim.x) dst[i] = src[i];
}

// ---------------- rmsnorm -> split bf16 -------------------------------------
__global__ void __launch_bounds__(256) rmsnorm_kernel(
    __nv_bfloat16* __restrict__ oh, __nv_bfloat16* __restrict__ ol,
    const float* __restrict__ in, const float* __restrict__ w) {
    const int t = blockIdx.x;
    const int tid = threadIdx.x;
    const float4* row = (const float4*)(in + (long long)t * Dc);
    float4 v0 = row[tid];
    float4 v1 = row[tid + 256];
    float ss = v0.x*v0.x + v0.y*v0.y + v0.z*v0.z + v0.w*v0.w
             + v1.x*v1.x + v1.y*v1.y + v1.z*v1.z + v1.w*v1.w;
    #pragma unroll
    for (int m = 16; m >= 1; m >>= 1) ss += __shfl_xor_sync(0xffffffffu, ss, m);
    __shared__ float red[8];
    __shared__ float s_inv;
    if ((tid & 31) == 0) red[tid >> 5] = ss;
    __syncthreads();
    if (tid == 0) {
        float tot = 0.f;
        #pragma unroll
        for (int i = 0; i < 8; ++i) tot += red[i];
        s_inv = rsqrtf(tot * (1.0f / (float)Dc) + 1e-6f);
    }
    __syncthreads();
    const float inv = s_inv;
    const float4* wv = (const float4*)w;
    float4 w0 = wv[tid], w1 = wv[tid + 256];
    float4 o0 = make_float4(v0.x*inv*w0.x, v0.y*inv*w0.y, v0.z*inv*w0.z, v0.w*inv*w0.w);
    float4 o1 = make_float4(v1.x*inv*w1.x, v1.y*inv*w1.y, v1.z*inv*w1.z, v1.w*inv*w1.w);
    const long long base = (long long)t * Dc;
    split_store4(oh, ol, base + tid * 4, o0);
    split_store4(oh, ol, base + (tid + 256) * 4, o1);
}

// ---------------- rmsnorm -> fp32 (for tf32 lm_head) ------------------------
__global__ void __launch_bounds__(256) rmsnorm_f32_kernel(
    float* __restrict__ out, const float* __restrict__ in,
    const float* __restrict__ w) {
    const int t = blockIdx.x;
    const int tid = threadIdx.x;
    const float4* row = (const float4*)(in + (long long)t * Dc);
    float4 v0 = row[tid];
    float4 v1 = row[tid + 256];
    float ss = v0.x*v0.x + v0.y*v0.y + v0.z*v0.z + v0.w*v0.w
             + v1.x*v1.x + v1.y*v1.y + v1.z*v1.z + v1.w*v1.w;
    #pragma unroll
    for (int m = 16; m >= 1; m >>= 1) ss += __shfl_xor_sync(0xffffffffu, ss, m);
    __shared__ float red[8];
    __shared__ float s_inv;
    if ((tid & 31) == 0) red[tid >> 5] = ss;
    __syncthreads();
    if (tid == 0) {
        float tot = 0.f;
        #pragma unroll
        for (int i = 0; i < 8; ++i) tot += red[i];
        s_inv = rsqrtf(tot * (1.0f / (float)Dc) + 1e-6f);
    }
    __syncthreads();
    const float inv = s_inv;
    const float4* wv = (const float4*)w;
    float4 w0 = wv[tid], w1 = wv[tid + 256];
    float4* op = (float4*)(out + (long long)t * Dc);
    float4 o0 = make_float4(v0.x*inv*w0.x, v0.y*inv*w0.y, v0.z*inv*w0.z, v0.w*inv*w0.w);
    float4 o1 = make_float4(v1.x*inv*w1.x, v1.y*inv*w1.y, v1.z*inv*w1.z, v1.w*inv*w1.w);
    op[tid] = o0; op[tid + 256] = o1;
}

// ---------------- rope ------------------------------------------------------
__global__ void rope_kernel(float* __restrict__ qkv, const int* __restrict__ pos) {
    const int idx = blockIdx.x * blockDim.x + threadIdx.x;
    if (idx >= Tc * Hc * (HDc / 2)) return;
    const int i  = idx & 63;
    const int hh = (idx >> 6) & (Hc - 1);
    const int t  = idx >> 10;
    const float freq = expf(-(float)i * (9.210340371976184f / 64.0f));
    const float ang  = (float)pos[t & (Sc - 1)] * freq;
    float s, c;
    sincosf(ang, &s, &c);
    const long long base = (long long)t * QKVc + hh * HDc + i;
    float q1 = qkv[base], q2 = qkv[base + 64];
    qkv[base]      = q1 * c - q2 * s;
    qkv[base + 64] = q2 * c + q1 * s;
    const long long kb = base + Dc;
    float k1 = qkv[kb], k2 = qkv[kb + 64];
    qkv[kb]      = k1 * c - k2 * s;
    qkv[kb + 64] = k2 * c + k1 * s;
}

// ---------------- bf16x3 NT GEMM: mma.sync + ldmatrix + cp.async (3-stage) --
#define PITCH       80
#define TILE_BYTES  (128*PITCH)      // 10240
#define STAGE_BYTES (4*TILE_BYTES)   // 40960: Ah, Al, Bh, Bl
#define GEMM_SMEM   (3*STAGE_BYTES)  // 122880

__device__ __forceinline__ void cp16(uint32_t dst, const void* src) {
    asm volatile("cp.async.cg.shared.global [%0], [%1], 16;" :: "r"(dst), "l"(src));
}
__device__ __forceinline__ void ldsm4(uint32_t* r, uint32_t addr) {
    asm volatile("ldmatrix.sync.aligned.m8n8.x4.shared.b16 {%0,%1,%2,%3}, [%4];"
                 : "=r"(r[0]), "=r"(r[1]), "=r"(r[2]), "=r"(r[3]) : "r"(addr));
}
__device__ __forceinline__ void ldsm2(uint32_t* r, uint32_t addr) {
    asm volatile("ldmatrix.sync.aligned.m8n8.x2.shared.b16 {%0,%1}, [%2];"
                 : "=r"(r[0]), "=r"(r[1]) : "r"(addr));
}
__device__ __forceinline__ void mma_bf16(float* c, const uint32_t* a, const uint32_t* b) {
    asm volatile(
        "mma.sync.aligned.m16n8k16.row.col.f32.bf16.bf16.f32 "
        "{%0,%1,%2,%3}, {%4,%5,%6,%7}, {%8,%9}, {%0,%1,%2,%3};"
        : "+f"(c[0]), "+f"(c[1]), "+f"(c[2]), "+f"(c[3])
        : "r"(a[0]), "r"(a[1]), "r"(a[2]), "r"(a[3]), "r"(b[0]), "r"(b[1]));
}

__device__ __forceinline__ void load_stage(
    uint32_t sb, int s,
    const __nv_bfloat16* __restrict__ Ah, const __nv_bfloat16* __restrict__ Al,
    const __nv_bfloat16* __restrict__ Bh, const __nv_bfloat16* __restrict__ Bl,
    long long bm, long long bn, long long K, long long k0, int tid) {
    const __nv_bfloat16* gs[4] = {Ah, Al, Bh, Bl};
    #pragma unroll
    for (int t = 0; t < 4; ++t) {
        const long long row0 = (t < 2) ? bm : bn;
        const __nv_bfloat16* g = gs[t];
        #pragma unroll
        for (int u = 0; u < 2; ++u) {
            const int ch = tid + (u << 8);      // 0..511
            const int r = ch >> 2, c = ch & 3;  // row, 16B chunk
            const uint32_t dst = sb + s * STAGE_BYTES + t * TILE_BYTES
                               + r * PITCH + c * 16;
            cp16(dst, g + (row0 + r) * K + k0 + c * 8);
        }
    }
}

__global__ void __launch_bounds__(256) gemm_bf16x3(
    const __nv_bfloat16* __restrict__ Ah, const __nv_bfloat16* __restrict__ Al,
    const __nv_bfloat16* __restrict__ Bh, const __nv_bfloat16* __restrict__ Bl,
    float* __restrict__ C, int M, int N, int K, int addres) {
    extern __shared__ char smraw[];
    const uint32_t sb = smem_u32(smraw);
    const int tid  = threadIdx.x;
    const int wid  = tid >> 5;
    const int lane = tid & 31;
    const int grp  = lane >> 2;
    const int qid  = lane & 3;
    const int m_base = (wid >> 2) * 64;
    const int n_base = (wid & 3) * 32;
    const long long bm = (long long)blockIdx.x * 128;
    const long long bn = (long long)blockIdx.y * 128;

    float acc[4][4][4];
    #pragma unroll
    for (int i = 0; i < 4; ++i)
        #pragma unroll
        for (int j = 0; j < 4; ++j)
            #pragma unroll
            for (int r = 0; r < 4; ++r) acc[i][j][r] = 0.f;

    const int nIter = K >> 5;
    load_stage(sb, 0, Ah, Al, Bh, Bl, bm, bn, K, 0, tid);
    asm volatile("cp.async.commit_group;" ::: "memory");
    load_stage(sb, 1, Ah, Al, Bh, Bl, bm, bn, K, 32, tid);
    asm volatile("cp.async.commit_group;" ::: "memory");

    const int arow = lane & 15, achunk = lane >> 4;
    const int brow = lane & 7,  bchunk = (lane >> 3) & 1;

    int stage = 0;
    for (int it = 0; it < nIter; ++it) {
        if (it + 1 < nIter) {
            asm volatile("cp.async.wait_group 1;" ::: "memory");
        } else {
            asm volatile("cp.async.wait_group 0;" ::: "memory");
        }
        __syncthreads();
        if (it + 2 < nIter) {
            int ns = stage + 2; if (ns >= 3) ns -= 3;
            load_stage(sb, ns, Ah, Al, Bh, Bl, bm, bn, K,
                       (long long)(it + 2) << 5, tid);
            asm volatile("cp.async.commit_group;" ::: "memory");
        }

        const uint32_t stb = sb + stage * STAGE_BYTES;
        #pragma unroll
        for (int ks = 0; ks < 2; ++ks) {
            uint32_t ah[4][4], al[4][4], bh[4][2], bl[4][2];
            #pragma unroll
            for (int mt = 0; mt < 4; ++mt) {
                const uint32_t ad = stb + (m_base + mt * 16 + arow) * PITCH
                                  + (ks * 2 + achunk) * 16;
                ldsm4(ah[mt], ad);
                ldsm4(al[mt], ad + TILE_BYTES);
            }
            #pragma unroll
            for (int nt = 0; nt < 4; ++nt) {
                const uint32_t bd = stb + 2 * TILE_BYTES
                                  + (n_base + nt * 8 + brow) * PITCH
                                  + (ks * 2 + bchunk) * 16;
                ldsm2(bh[nt], bd);
                ldsm2(bl[nt], bd + TILE_BYTES);
            }
            #pragma unroll
            for (int mt = 0; mt < 4; ++mt)
                #pragma unroll
                for (int nt = 0; nt < 4; ++nt) {
                    mma_bf16(acc[mt][nt], ah[mt], bh[nt]);
                    mma_bf16(acc[mt][nt], ah[mt], bl[nt]);
                    mma_bf16(acc[mt][nt], al[mt], bh[nt]);
                }
        }
        if (++stage == 3) stage = 0;
    }

    #pragma unroll
    for (int mt = 0; mt < 4; ++mt) {
        #pragma unroll
        for (int nt = 0; nt < 4; ++nt) {
            const long long row = bm + m_base + mt * 16 + grp;
            const long long col = bn + n_base + nt * 8 + 2 * qid;
            float* c = acc[mt][nt];
            if (addres) {
                float2 r0 = *(const float2*)&C[row * N + col];
                float2 r1 = *(const float2*)&C[(row + 8) * N + col];
                c[0] += r0.x; c[1] += r0.y; c[2] += r1.x; c[3] += r1.y;
            }
            *(float2*)&C[row * N + col]       = make_float2(c[0], c[1]);
            *(float2*)&C[(row + 8) * N + col] = make_float2(c[2], c[3]);
        }
    }
}

// ---------------- tf32 NT GEMM (terminal lm_head only) ----------------------
__device__ __forceinline__ unsigned f2tf32(float x) {
    unsigned r;
    asm("cvt.rna.tf32.f32 %0, %1;" : "=r"(r) : "f"(x));
    return r;
}
__device__ __forceinline__ void mma_tf32(float* c, const unsigned* a, const unsigned* b) {
    asm volatile(
        "mma.sync.aligned.m16n8k8.row.col.f32.tf32.tf32.f32 "
        "{%0,%1,%2,%3}, {%4,%5,%6,%7}, {%8,%9}, {%0,%1,%2,%3};"
        : "+f"(c[0]), "+f"(c[1]), "+f"(c[2]), "+f"(c[3])
        : "r"(a[0]), "r"(a[1]), "r"(a[2]), "r"(a[3]), "r"(b[0]), "r"(b[1]));
}
#define BKP 20
__global__ void __launch_bounds__(256) gemm_tf32(
    const float* __restrict__ A, const float* __restrict__ B,
    float* __restrict__ C, int M, int N, int K) {
    __shared__ unsigned As[128][BKP];
    __shared__ unsigned Bs[128][BKP];
    const int tid  = threadIdx.x;
    const int wid  = tid >> 5;
    const int lane = tid & 31;
    const int grp  = lane >> 2;
    const int qid  = lane & 3;
    const int m_base = (wid >> 2) * 64;
    const int n_base = (wid & 3) * 32;
    const int bm = blockIdx.x * 128;
    const int bn = blockIdx.y * 128;
    const int lr = tid >> 2;
    const int lk = (tid & 3) << 2;

    const float* Ap  = A + (long long)(bm + lr) * K + lk;
    const float* Ap2 = Ap + (long long)64 * K;
    const float* Bp  = B + (long long)(bn + lr) * K + lk;
    const float* Bp2 = Bp + (long long)64 * K;

    float acc[4][4][4];
    #pragma unroll
    for (int i = 0; i < 4; ++i)
        #pragma unroll
        for (int j = 0; j < 4; ++j)
            #pragma unroll
            for (int r = 0; r < 4; ++r) acc[i][j][r] = 0.f;

    const int nt_iter = K >> 4;
    for (int t = 0; t < nt_iter; ++t) {
        const int k0 = t << 4;
        float4 a0 = *(const float4*)(Ap  + k0);
        float4 a1 = *(const float4*)(Ap2 + k0);
        float4 b0 = *(const float4*)(Bp  + k0);
        float4 b1 = *(const float4*)(Bp2 + k0);
        __syncthreads();
        *(uint4*)&As[lr][lk]      = make_uint4(f2tf32(a0.x), f2tf32(a0.y), f2tf32(a0.z), f2tf32(a0.w));
        *(uint4*)&As[lr + 64][lk] = make_uint4(f2tf32(a1.x), f2tf32(a1.y), f2tf32(a1.z), f2tf32(a1.w));
        *(uint4*)&Bs[lr][lk]      = make_uint4(f2tf32(b0.x), f2tf32(b0.y), f2tf32(b0.z), f2tf32(b0.w));
        *(uint4*)&Bs[lr + 64][lk] = make_uint4(f2tf32(b1.x), f2tf32(b1.y), f2tf32(b1.z), f2tf32(b1.w));
        __syncthreads();
        #pragma unroll
        for (int ks = 0; ks < 16; ks += 8) {
            unsigned afr[4][4];
            #pragma unroll
            for (int mt = 0; mt < 4; ++mt) {
                const int row = m_base + mt * 16 + grp;
                afr[mt][0] = As[row][ks + qid];
                afr[mt][1] = As[row + 8][ks + qid];
                afr[mt][2] = As[row][ks + qid + 4];
                afr[mt][3] = As[row + 8][ks + qid + 4];
            }
            unsigned bfr[4][2];
            #pragma unroll
            for (int nt = 0; nt < 4; ++nt) {
                const int col = n_base + nt * 8 + grp;
                bfr[nt][0] = Bs[col][ks + qid];
                bfr[nt][1] = Bs[col][ks + qid + 4];
            }
            #pragma unroll
            for (int mt = 0; mt < 4; ++mt)
                #pragma unroll
                for (int nt = 0; nt < 4; ++nt)
                    mma_tf32(acc[mt][nt], afr[mt], bfr[nt]);
        }
    }

    #pragma unroll
    for (int mt = 0; mt < 4; ++mt) {
        #pragma unroll
        for (int nt = 0; nt < 4; ++nt) {
            const int row = bm + m_base + mt * 16 + grp;
            const int col = bn + n_base + nt * 8 + 2 * qid;
            float* c = acc[mt][nt];
            *(float2*)&C[(long long)row * N + col]       = make_float2(c[0], c[1]);
            *(float2*)&C[(long long)(row + 8) * N + col] = make_float2(c[2], c[3]);
        }
    }
}

// ---------------- flash attention (fp32) -> split bf16 output ---------------
#define QPAD 68
#define VPAD 132
#define ATTN_SMEM ((128*QPAD*2 + 64*VPAD + 64*QPAD + 192) * 4)

__global__ void __launch_bounds__(256) attn_kernel(
    const float* __restrict__ qkv,
    __nv_bfloat16* __restrict__ oh, __nv_bfloat16* __restrict__ ol) {
    extern __shared__ float sm[];
    float* Qt    = sm;
    float* Kt    = Qt + 128 * QPAD;
    float* Vs    = Kt + 128 * QPAD;
    float* Ps    = Vs + 64 * VPAD;
    float* sm_m  = Ps + 64 * QPAD;
    float* sm_l  = sm_m + 64;
    float* sm_sc = sm_l + 64;

    const int qt = (int)gridDim.x - 1 - (int)blockIdx.x;
    const int hh = blockIdx.y;
    const int b  = blockIdx.z;
    const int tid = threadIdx.x;
    const int ty = tid >> 4, tx = tid & 15;
    const int r0 = ty << 2;
    const int c0 = tx << 2;
    const int co = tx << 3;
    const int tok0 = b * Sc + qt * 64;
    const float scale = 0.08838834764831845f;

    for (int idx = tid; idx < 64 * 128; idx += 256) {
        const int r = idx >> 7, d = idx & 127;
        Qt[d * QPAD + r] = qkv[(long long)(tok0 + r) * QKVc + hh * HDc + d] * scale;
    }
    if (tid < 64) { sm_m[tid] = -3.0e38f; sm_l[tid] = 0.f; }

    float acc[4][8];
    #pragma unroll
    for (int i = 0; i < 4; ++i)
        #pragma unroll
        for (int j = 0; j < 8; ++j) acc[i][j] = 0.f;
    __syncthreads();

    for (int kt = 0; kt <= qt; ++kt) {
        const int ktok = b * Sc + kt * 64;
        for (int idx = tid; idx < 64 * 128; idx += 256) {
            const int r = idx >> 7, d = idx & 127;
            const long long g = (long long)(ktok + r) * QKVc + hh * HDc + d;
            Kt[d * QPAD + r] = qkv[g + Dc];
            Vs[r * VPAD + d] = qkv[g + 2 * Dc];
        }
        __syncthreads();

        float s[4][4];
        #pragma unroll
        for (int i = 0; i < 4; ++i)
            #pragma unroll
            for (int j = 0; j < 4; ++j) s[i][j] = 0.f;

        #pragma unroll 4
        for (int k = 0; k < 128; ++k) {
            float4 a  = *(const float4*)&Qt[k * QPAD + r0];
            float4 bb = *(const float4*)&Kt[k * QPAD + c0];
            float av[4] = {a.x, a.y, a.z, a.w};
            float bv[4] = {bb.x, bb.y, bb.z, bb.w};
            #pragma unroll
            for (int i = 0; i < 4; ++i)
                #pragma unroll
                for (int j = 0; j < 4; ++j) s[i][j] += av[i] * bv[j];
        }
        if (kt == qt) {
            #pragma unroll
            for (int i = 0; i < 4; ++i)
                #pragma unroll
                for (int j = 0; j < 4; ++j)
                    if (c0 + j > r0 + i) s[i][j] = -3.0e38f;
        }

        #pragma unroll
        for (int i = 0; i < 4; ++i) {
            const int row = r0 + i;
            float mloc = fmaxf(fmaxf(s[i][0], s[i][1]), fmaxf(s[i][2], s[i][3]));
            #pragma unroll
            for (int m = 8; m >= 1; m >>= 1)
                mloc = fmaxf(mloc, __shfl_xor_sync(0xffffffffu, mloc, m));
            const float mold = sm_m[row];
            const float mnew = fmaxf(mold, mloc);
            float rsum = 0.f;
            #pragma unroll
            for (int j = 0; j < 4; ++j) {
                const float p = expf(s[i][j] - mnew);
                s[i][j] = p; rsum += p;
            }
            #pragma unroll
            for (int m = 8; m >= 1; m >>= 1)
                rsum += __shfl_xor_sync(0xffffffffu, rsum, m);
            if (tx == 0) {
                const float esc = expf(mold - mnew);
                sm_sc[row] = esc;
                sm_l[row]  = sm_l[row] * esc + rsum;
                sm_m[row]  = mnew;
            }
            *(float4*)&Ps[row * QPAD + c0] = make_float4(s[i][0], s[i][1], s[i][2], s[i][3]);
        }
        __syncthreads();

        #pragma unroll
        for (int i = 0; i < 4; ++i) {
            const float esc = sm_sc[r0 + i];
            #pragma unroll
            for (int j = 0; j < 8; ++j) acc[i][j] *= esc;
        }
        #pragma unroll 2
        for (int j = 0; j < 64; ++j) {
            float4 v0 = *(const float4*)&Vs[j * VPAD + co];
            float4 v1 = *(const float4*)&Vs[j * VPAD + co + 4];
            float pv[4];
            #pragma unroll
            for (int i = 0; i < 4; ++i) pv[i] = Ps[(r0 + i) * QPAD + j];
            #pragma unroll
            for (int i = 0; i < 4; ++i) {
                acc[i][0] += pv[i] * v0.x; acc[i][1] += pv[i] * v0.y;
                acc[i][2] += pv[i] * v0.z; acc[i][3] += pv[i] * v0.w;
                acc[i][4] += pv[i] * v1.x; acc[i][5] += pv[i] * v1.y;
                acc[i][6] += pv[i] * v1.z; acc[i][7] += pv[i] * v1.w;
            }
        }
        __syncthreads();
    }

    #pragma unroll
    for (int i = 0; i < 4; ++i) {
        const float linv = 1.f / sm_l[r0 + i];
        const long long ob = (long long)(tok0 + r0 + i) * Dc + hh * HDc + co;
        float4 v0 = make_float4(acc[i][0]*linv, acc[i][1]*linv, acc[i][2]*linv, acc[i][3]*linv);
        float4 v1 = make_float4(acc[i][4]*linv, acc[i][5]*linv, acc[i][6]*linv, acc[i][7]*linv);
        split_store4(oh, ol, ob, v0);
        split_store4(oh, ol, ob + 4, v1);
    }
}

// ---------------- silu(gate)*up -> split bf16 -------------------------------
__global__ void silu_kernel(__nv_bfloat16* __restrict__ ah,
                            __nv_bfloat16* __restrict__ al,
                            const float* __restrict__ gu) {
    const long long idx = ((long long)blockIdx.x * blockDim.x + threadIdx.x) * 4;
    if (idx >= (long long)Tc * Ic) return;
    const int t = (int)(idx / Ic);
    const int i = (int)(idx - (long long)t * Ic);
    float4 g = *(const float4*)(gu + (long long)t * GUc + i);
    float4 u = *(const float4*)(gu + (long long)t * GUc + Ic + i);
    float4 a;
    a.x = (g.x / (1.f + expf(-g.x))) * u.x;
    a.y = (g.y / (1.f + expf(-g.y))) * u.y;
    a.z = (g.z / (1.f + expf(-g.z))) * u.z;
    a.w = (g.w / (1.f + expf(-g.w))) * u.w;
    split_store4(ah, al, idx, a);
}

// ---------------- launch ----------------------------------------------------
extern "C" void kernel_launch(void* const* d_in, const int* in_sizes, int n_in,
                              void* d_out, int out_size) {
    const int*   ids    = (const int*)  d_in[0];
    const int*   pos    = (const int*)  d_in[1];
    const float* embed  = (const float*)d_in[2];
    const float* Wqkv   = (const float*)d_in[3];
    const float* Wo     = (const float*)d_in[4];
    const float* Wgu    = (const float*)d_in[5];
    const float* Wd     = (const float*)d_in[6];
    const float* ln1    = (const float*)d_in[7];
    const float* ln2    = (const float*)d_in[8];
    const float* norm_w = (const float*)d_in[9];
    const float* lmh    = (const float*)d_in[10];
    float* out = (float*)d_out;

    float *h, *qkv, *gu;
    __nv_bfloat16 *xh, *xl, *oh, *ol, *ah, *al;
    __nv_bfloat16 *wqkvh, *wqkvl, *woh, *wol, *wguh, *wgul, *wdh, *wdl;
    cudaGetSymbolAddress((void**)&h,   g_h);
    cudaGetSymbolAddress((void**)&qkv, g_qkv);
    cudaGetSymbolAddress((void**)&gu,  g_gu);
    cudaGetSymbolAddress((void**)&xh,  g_xh);  cudaGetSymbolAddress((void**)&xl, g_xl);
    cudaGetSymbolAddress((void**)&oh,  g_oh);  cudaGetSymbolAddress((void**)&ol, g_ol);
    cudaGetSymbolAddress((void**)&ah,  g_ah);  cudaGetSymbolAddress((void**)&al, g_al);
    cudaGetSymbolAddress((void**)&wqkvh, g_wqkvh); cudaGetSymbolAddress((void**)&wqkvl, g_wqkvl);
    cudaGetSymbolAddress((void**)&woh,   g_woh);   cudaGetSymbolAddress((void**)&wol,   g_wol);
    cudaGetSymbolAddress((void**)&wguh,  g_wguh);  cudaGetSymbolAddress((void**)&wgul,  g_wgul);
    cudaGetSymbolAddress((void**)&wdh,   g_wdh);   cudaGetSymbolAddress((void**)&wdl,   g_wdl);

    cudaFuncSetAttribute(attn_kernel,
                         cudaFuncAttributeMaxDynamicSharedMemorySize, ATTN_SMEM);
    cudaFuncSetAttribute(gemm_bf16x3,
                         cudaFuncAttributeMaxDynamicSharedMemorySize, GEMM_SMEM);

    // split per-layer weights into bf16 hi/lo (lm_head stays fp32 -> tf32 path)
    {
        const long long n1 = (long long)Lc*QKVc*Dc, n2 = (long long)Lc*Dc*Dc,
                        n3 = (long long)Lc*GUc*Dc,  n4 = (long long)Lc*Dc*Ic;
        split_kernel<<<(unsigned)((n1/4 + 255)/256), 256>>>(Wqkv, wqkvh, wqkvl, n1);
        split_kernel<<<(unsigned)((n2/4 + 255)/256), 256>>>(Wo,   woh,   wol,   n2);
        split_kernel<<<(unsigned)((n3/4 + 255)/256), 256>>>(Wgu,  wguh,  wgul,  n3);
        split_kernel<<<(unsigned)((n4/4 + 255)/256), 256>>>(Wd,   wdh,   wdl,   n4);
    }

    embed_kernel<<<Tc, 128>>>(ids, embed, h);

    for (int l = 0; l < Lc; ++l) {
        rmsnorm_kernel<<<Tc, 256>>>(xh, xl, h, ln1 + (long long)l * Dc);
        gemm_bf16x3<<<dim3(Tc/128, QKVc/128), 256, GEMM_SMEM>>>(
            xh, xl, wqkvh + (long long)l*QKVc*Dc, wqkvl + (long long)l*QKVc*Dc,
            qkv, Tc, QKVc, Dc, 0);
        rope_kernel<<<(Tc * Hc * 64 + 255) / 256, 256>>>(qkv, pos);
        attn_kernel<<<dim3(Sc / 64, Hc, Bc), 256, ATTN_SMEM>>>(qkv, oh, ol);
        gemm_bf16x3<<<dim3(Tc/128, Dc/128), 256, GEMM_SMEM>>>(
            oh, ol, woh + (long long)l*Dc*Dc, wol + (long long)l*Dc*Dc,
            h, Tc, Dc, Dc, 1);
        rmsnorm_kernel<<<Tc, 256>>>(xh, xl, h, ln2 + (long long)l * Dc);
        gemm_bf16x3<<<dim3(Tc/128, GUc/128), 256, GEMM_SMEM>>>(
            xh, xl, wguh + (long long)l*GUc*Dc, wgul + (long long)l*GUc*Dc,
            gu, Tc, GUc, Dc, 0);
        silu_kernel<<<(unsigned)(((long long)Tc*Ic/4 + 255)/256), 256>>>(ah, al, gu);
        gemm_bf16x3<<<dim3(Tc/128, Dc/128), 256, GEMM_SMEM>>>(
            ah, al, wdh + (long long)l*Dc*Ic, wdl + (long long)l*Dc*Ic,
            h, Tc, Dc, Ic, 1);
    }

    // final norm (fp32) + tf32 lm_head (terminal: error does not compound)
    rmsnorm_f32_kernel<<<Tc, 256>>>(qkv, h, norm_w);
    gemm_tf32<<<dim3(Tc/128, Vc/128), 256>>>(qkv, lmh, out, Tc, Vc, Dc);
}

// round 13
// speedup vs baseline: 1.2152x; 1.2152x over previous
#include <cuda_runtime.h>
#include <cuda_bf16.h>
#include <cstdint>

// Model dims
#define Lc   4
#define Dc   2048
#define Hc   16
#define HDc  128
#define Ic   5632
#define Vc   32000
#define Bc   2
#define Sc   1024
#define Tc   (Bc*Sc)        // 2048 tokens
#define QKVc (3*Hc*HDc)     // 6144
#define GUc  (2*Ic)         // 11264

// ---------------- scratch (static device globals; no allocations) ----------
__device__ float g_h  [Tc*Dc];     // residual (fp32)
__device__ float g_qkv[Tc*QKVc];   // qkv fp32 (attention input)
__device__ float g_gu [Tc*GUc];    // gate+up fp32

// split activations (bf16 hi/lo)
__device__ __nv_bfloat16 g_xh[Tc*Dc],  g_xl[Tc*Dc];
__device__ __nv_bfloat16 g_oh[Tc*Dc],  g_ol[Tc*Dc];
__device__ __nv_bfloat16 g_ah[Tc*Ic],  g_al[Tc*Ic];

// split weights (bf16 hi/lo)
__device__ __nv_bfloat16 g_wqkvh[Lc*QKVc*Dc], g_wqkvl[Lc*QKVc*Dc];
__device__ __nv_bfloat16 g_woh  [Lc*Dc*Dc],   g_wol  [Lc*Dc*Dc];
__device__ __nv_bfloat16 g_wguh [Lc*GUc*Dc],  g_wgul [Lc*GUc*Dc];
__device__ __nv_bfloat16 g_wdh  [Lc*Dc*Ic],   g_wdl  [Lc*Dc*Ic];
__device__ __nv_bfloat16 g_lmhh [Vc*Dc],      g_lmhl [Vc*Dc];

// ---------------- small helpers --------------------------------------------
__device__ __forceinline__ uint32_t smem_u32(const void* p) {
    uint32_t a;
    asm("{ .reg .u64 t; cvta.to.shared.u64 t, %1; cvt.u32.u64 %0, t; }"
        : "=r"(a) : "l"(p));
    return a;
}
__device__ __forceinline__ void split_store4(__nv_bfloat16* hp, __nv_bfloat16* lp,
                                             long long off, float4 v) {
    __nv_bfloat16 h0 = __float2bfloat16(v.x), h1 = __float2bfloat16(v.y);
    __nv_bfloat16 h2 = __float2bfloat16(v.z), h3 = __float2bfloat16(v.w);
    __nv_bfloat16 l0 = __float2bfloat16(v.x - __bfloat162float(h0));
    __nv_bfloat16 l1 = __float2bfloat16(v.y - __bfloat162float(h1));
    __nv_bfloat16 l2 = __float2bfloat16(v.z - __bfloat162float(h2));
    __nv_bfloat16 l3 = __float2bfloat16(v.w - __bfloat162float(h3));
    *(ushort4*)(hp + off) = make_ushort4(__bfloat16_as_ushort(h0), __bfloat16_as_ushort(h1),
                                         __bfloat16_as_ushort(h2), __bfloat16_as_ushort(h3));
    *(ushort4*)(lp + off) = make_ushort4(__bfloat16_as_ushort(l0), __bfloat16_as_ushort(l1),
                                         __bfloat16_as_ushort(l2), __bfloat16_as_ushort(l3));
}
__device__ __forceinline__ void split_pack2(float a, float b,
                                            uint32_t& h, uint32_t& l) {
    __nv_bfloat16 ha = __float2bfloat16(a), hb = __float2bfloat16(b);
    __nv_bfloat16 la = __float2bfloat16(a - __bfloat162float(ha));
    __nv_bfloat16 lb = __float2bfloat16(b - __bfloat162float(hb));
    h = (uint32_t)__bfloat16_as_ushort(ha) | ((uint32_t)__bfloat16_as_ushort(hb) << 16);
    l = (uint32_t)__bfloat16_as_ushort(la) | ((uint32_t)__bfloat16_as_ushort(lb) << 16);
}

// ---------------- weight split ---------------------------------------------
__global__ void split_kernel(const float* __restrict__ s,
                             __nv_bfloat16* __restrict__ hp,
                             __nv_bfloat16* __restrict__ lp, long long n) {
    long long i = ((long long)blockIdx.x * blockDim.x + threadIdx.x) * 4;
    if (i >= n) return;
    split_store4(hp, lp, i, *(const float4*)(s + i));
}

// ---------------- embedding gather -----------------------------------------
__global__ void embed_kernel(const int* __restrict__ ids,
                             const float* __restrict__ emb,
                             float* __restrict__ h) {
    const int t = blockIdx.x;
    const int id = ids[t];
    const float4* src = (const float4*)(emb + (long long)id * Dc);
    float4* dst = (float4*)(h + (long long)t * Dc);
    for (int i = threadIdx.x; i < Dc / 4; i += blockDim.x) dst[i] = src[i];
}

// ---------------- rmsnorm -> split bf16 -------------------------------------
__global__ void __launch_bounds__(256) rmsnorm_kernel(
    __nv_bfloat16* __restrict__ oh, __nv_bfloat16* __restrict__ ol,
    const float* __restrict__ in, const float* __restrict__ w) {
    const int t = blockIdx.x;
    const int tid = threadIdx.x;
    const float4* row = (const float4*)(in + (long long)t * Dc);
    float4 v0 = row[tid];
    float4 v1 = row[tid + 256];
    float ss = v0.x*v0.x + v0.y*v0.y + v0.z*v0.z + v0.w*v0.w
             + v1.x*v1.x + v1.y*v1.y + v1.z*v1.z + v1.w*v1.w;
    #pragma unroll
    for (int m = 16; m >= 1; m >>= 1) ss += __shfl_xor_sync(0xffffffffu, ss, m);
    __shared__ float red[8];
    __shared__ float s_inv;
    if ((tid & 31) == 0) red[tid >> 5] = ss;
    __syncthreads();
    if (tid == 0) {
        float tot = 0.f;
        #pragma unroll
        for (int i = 0; i < 8; ++i) tot += red[i];
        s_inv = rsqrtf(tot * (1.0f / (float)Dc) + 1e-6f);
    }
    __syncthreads();
    const float inv = s_inv;
    const float4* wv = (const float4*)w;
    float4 w0 = wv[tid], w1 = wv[tid + 256];
    float4 o0 = make_float4(v0.x*inv*w0.x, v0.y*inv*w0.y, v0.z*inv*w0.z, v0.w*inv*w0.w);
    float4 o1 = make_float4(v1.x*inv*w1.x, v1.y*inv*w1.y, v1.z*inv*w1.z, v1.w*inv*w1.w);
    const long long base = (long long)t * Dc;
    split_store4(oh, ol, base + tid * 4, o0);
    split_store4(oh, ol, base + (tid + 256) * 4, o1);
}

// ---------------- rope ------------------------------------------------------
__global__ void rope_kernel(float* __restrict__ qkv, const int* __restrict__ pos) {
    const int idx = blockIdx.x * blockDim.x + threadIdx.x;
    if (idx >= Tc * Hc * (HDc / 2)) return;
    const int i  = idx & 63;
    const int hh = (idx >> 6) & (Hc - 1);
    const int t  = idx >> 10;
    const float freq = expf(-(float)i * (9.210340371976184f / 64.0f));
    const float ang  = (float)pos[t & (Sc - 1)] * freq;
    float s, c;
    sincosf(ang, &s, &c);
    const long long base = (long long)t * QKVc + hh * HDc + i;
    float q1 = qkv[base], q2 = qkv[base + 64];
    qkv[base]      = q1 * c - q2 * s;
    qkv[base + 64] = q2 * c + q1 * s;
    const long long kb = base + Dc;
    float k1 = qkv[kb], k2 = qkv[kb + 64];
    qkv[kb]      = k1 * c - k2 * s;
    qkv[kb + 64] = k2 * c + k1 * s;
}

// ---------------- bf16x3 NT GEMM (R10 winner: 2-stage cp.async + ldmatrix) --
#define PITCH       80
#define TILE_BYTES  (128*PITCH)      // 10240
#define STAGE_BYTES (4*TILE_BYTES)   // 40960: Ah, Al, Bh, Bl
#define GEMM_SMEM   (2*STAGE_BYTES)  // 81920 -> 2 CTAs/SM

__device__ __forceinline__ void cp16(uint32_t dst, const void* src) {
    asm volatile("cp.async.cg.shared.global [%0], [%1], 16;" :: "r"(dst), "l"(src));
}
__device__ __forceinline__ void ldsm4(uint32_t* r, uint32_t addr) {
    asm volatile("ldmatrix.sync.aligned.m8n8.x4.shared.b16 {%0,%1,%2,%3}, [%4];"
                 : "=r"(r[0]), "=r"(r[1]), "=r"(r[2]), "=r"(r[3]) : "r"(addr));
}
__device__ __forceinline__ void ldsm2(uint32_t* r, uint32_t addr) {
    asm volatile("ldmatrix.sync.aligned.m8n8.x2.shared.b16 {%0,%1}, [%2];"
                 : "=r"(r[0]), "=r"(r[1]) : "r"(addr));
}
__device__ __forceinline__ void mma_bf16(float* c, const uint32_t* a, const uint32_t* b) {
    asm volatile(
        "mma.sync.aligned.m16n8k16.row.col.f32.bf16.bf16.f32 "
        "{%0,%1,%2,%3}, {%4,%5,%6,%7}, {%8,%9}, {%0,%1,%2,%3};"
        : "+f"(c[0]), "+f"(c[1]), "+f"(c[2]), "+f"(c[3])
        : "r"(a[0]), "r"(a[1]), "r"(a[2]), "r"(a[3]), "r"(b[0]), "r"(b[1]));
}

__device__ __forceinline__ void load_stage(
    uint32_t sb, int s,
    const __nv_bfloat16* __restrict__ Ah, const __nv_bfloat16* __restrict__ Al,
    const __nv_bfloat16* __restrict__ Bh, const __nv_bfloat16* __restrict__ Bl,
    long long bm, long long bn, long long K, long long k0, int tid) {
    const __nv_bfloat16* gs[4] = {Ah, Al, Bh, Bl};
    #pragma unroll
    for (int t = 0; t < 4; ++t) {
        const long long row0 = (t < 2) ? bm : bn;
        const __nv_bfloat16* g = gs[t];
        #pragma unroll
        for (int u = 0; u < 2; ++u) {
            const int ch = tid + (u << 8);      // 0..511
            const int r = ch >> 2, c = ch & 3;  // row, 16B chunk
            const uint32_t dst = sb + s * STAGE_BYTES + t * TILE_BYTES
                               + r * PITCH + c * 16;
            cp16(dst, g + (row0 + r) * K + k0 + c * 8);
        }
    }
}

__global__ void __launch_bounds__(256) gemm_bf16x3(
    const __nv_bfloat16* __restrict__ Ah, const __nv_bfloat16* __restrict__ Al,
    const __nv_bfloat16* __restrict__ Bh, const __nv_bfloat16* __restrict__ Bl,
    float* __restrict__ C, int M, int N, int K, int addres) {
    extern __shared__ char smraw[];
    const uint32_t sb = smem_u32(smraw);
    const int tid  = threadIdx.x;
    const int wid  = tid >> 5;
    const int lane = tid & 31;
    const int grp  = lane >> 2;
    const int qid  = lane & 3;
    const int m_base = (wid >> 2) * 64;
    const int n_base = (wid & 3) * 32;
    const long long bm = (long long)blockIdx.x * 128;
    const long long bn = (long long)blockIdx.y * 128;

    float acc[4][4][4];
    #pragma unroll
    for (int i = 0; i < 4; ++i)
        #pragma unroll
        for (int j = 0; j < 4; ++j)
            #pragma unroll
            for (int r = 0; r < 4; ++r) acc[i][j][r] = 0.f;

    const int nIter = K >> 5;
    load_stage(sb, 0, Ah, Al, Bh, Bl, bm, bn, K, 0, tid);
    asm volatile("cp.async.commit_group;" ::: "memory");

    const int arow = lane & 15, achunk = lane >> 4;
    const int brow = lane & 7,  bchunk = (lane >> 3) & 1;

    for (int it = 0; it < nIter; ++it) {
        const int s = it & 1;
        if (it + 1 < nIter) {
            load_stage(sb, s ^ 1, Ah, Al, Bh, Bl, bm, bn, K,
                       (long long)(it + 1) << 5, tid);
            asm volatile("cp.async.commit_group;" ::: "memory");
            asm volatile("cp.async.wait_group 1;" ::: "memory");
        } else {
            asm volatile("cp.async.wait_group 0;" ::: "memory");
        }
        __syncthreads();

        const uint32_t stb = sb + s * STAGE_BYTES;
        #pragma unroll
        for (int ks = 0; ks < 2; ++ks) {
            uint32_t ah[4][4], al[4][4], bh[4][2], bl[4][2];
            #pragma unroll
            for (int mt = 0; mt < 4; ++mt) {
                const uint32_t ad = stb + (m_base + mt * 16 + arow) * PITCH
                                  + (ks * 2 + achunk) * 16;
                ldsm4(ah[mt], ad);
                ldsm4(al[mt], ad + TILE_BYTES);
            }
            #pragma unroll
            for (int nt = 0; nt < 4; ++nt) {
                const uint32_t bd = stb + 2 * TILE_BYTES
                                  + (n_base + nt * 8 + brow) * PITCH
                                  + (ks * 2 + bchunk) * 16;
                ldsm2(bh[nt], bd);
                ldsm2(bl[nt], bd + TILE_BYTES);
            }
            #pragma unroll
            for (int mt = 0; mt < 4; ++mt)
                #pragma unroll
                for (int nt = 0; nt < 4; ++nt) {
                    mma_bf16(acc[mt][nt], ah[mt], bh[nt]);
                    mma_bf16(acc[mt][nt], ah[mt], bl[nt]);
                    mma_bf16(acc[mt][nt], al[mt], bh[nt]);
                }
        }
        __syncthreads();
    }

    #pragma unroll
    for (int mt = 0; mt < 4; ++mt) {
        #pragma unroll
        for (int nt = 0; nt < 4; ++nt) {
            const long long row = bm + m_base + mt * 16 + grp;
            const long long col = bn + n_base + nt * 8 + 2 * qid;
            float* c = acc[mt][nt];
            if (addres) {
                float2 r0 = *(const float2*)&C[row * N + col];
                float2 r1 = *(const float2*)&C[(row + 8) * N + col];
                c[0] += r0.x; c[1] += r0.y; c[2] += r1.x; c[3] += r1.y;
            }
            *(float2*)&C[row * N + col]       = make_float2(c[0], c[1]);
            *(float2*)&C[(row + 8) * N + col] = make_float2(c[2], c[3]);
        }
    }
}

// ---------------- tensor-core flash attention (bf16x3) ----------------------
// CTA: 128 q-rows x 1 head. 8 warps x 16 rows => warp-local softmax.
// S = (Qh+Ql)(Kh+Kl)^T (3 MMAs), P split hi/lo, O += (Ph+Pl)(Vh+Vl) (3 MMAs).
#define AQP 272   // Q row pitch: 128 bf16 = 256B + 16 pad
#define AKP 272   // K row pitch
#define AVP 144   // V^T row pitch: 64 bf16 = 128B + 16 pad
#define OFF_QH 0
#define OFF_QL (128*AQP)
#define OFF_KH (2*128*AQP)
#define OFF_KL (OFF_KH + 64*AKP)
#define OFF_VH (OFF_KL + 64*AKP)
#define OFF_VL (OFF_VH + 128*AVP)
#define ATTN_SMEM (OFF_VL + 128*AVP)   // 141312 bytes

__global__ void __launch_bounds__(256) attn_kernel(
    const float* __restrict__ qkv,
    __nv_bfloat16* __restrict__ oh, __nv_bfloat16* __restrict__ ol) {
    extern __shared__ char sm[];
    const uint32_t sb = smem_u32(sm);
    const int tid = threadIdx.x, wid = tid >> 5, lane = tid & 31;
    const int grp = lane >> 2, qid = lane & 3;
    const int qt = (int)gridDim.x - 1 - (int)blockIdx.x;  // heavy first
    const int hh = blockIdx.y, b = blockIdx.z;
    const int q0 = qt * 128;
    const int tok0 = b * Sc + q0;
    const float scale = 0.08838834764831845f;

    // load Q (pre-scaled, split hi/lo)
    for (int idx = tid; idx < 128 * 128; idx += 256) {
        const int r = idx >> 7, d = idx & 127;
        const float v = qkv[(long long)(tok0 + r) * QKVc + hh * HDc + d] * scale;
        const __nv_bfloat16 h = __float2bfloat16(v);
        const __nv_bfloat16 l = __float2bfloat16(v - __bfloat162float(h));
        *(unsigned short*)(sm + OFF_QH + r * AQP + d * 2) = __bfloat16_as_ushort(h);
        *(unsigned short*)(sm + OFF_QL + r * AQP + d * 2) = __bfloat16_as_ushort(l);
    }

    float of[16][4];
    #pragma unroll
    for (int n = 0; n < 16; ++n)
        #pragma unroll
        for (int r = 0; r < 4; ++r) of[n][r] = 0.f;
    float m0 = -3.0e38f, m1 = -3.0e38f, l0 = 0.f, l1 = 0.f;

    const int arow = lane & 15, achunk = lane >> 4;
    const int brow = lane & 7,  bchunk = (lane >> 3) & 1;
    const int rb = q0 + wid * 16;          // warp's global row base
    const int n_tiles = (q0 >> 6) + 2;

    for (int kt = 0; kt < n_tiles; ++kt) {
        __syncthreads();
        const int ktok = b * Sc + kt * 64;
        for (int idx = tid; idx < 64 * 128; idx += 256) {
            const int r = idx >> 7, d = idx & 127;
            const long long gk = (long long)(ktok + r) * QKVc + Dc + hh * HDc + d;
            const float kv = qkv[gk];
            __nv_bfloat16 h = __float2bfloat16(kv);
            __nv_bfloat16 l = __float2bfloat16(kv - __bfloat162float(h));
            *(unsigned short*)(sm + OFF_KH + r * AKP + d * 2) = __bfloat16_as_ushort(h);
            *(unsigned short*)(sm + OFF_KL + r * AKP + d * 2) = __bfloat16_as_ushort(l);
            const float vv = qkv[gk + Dc];
            h = __float2bfloat16(vv);
            l = __float2bfloat16(vv - __bfloat162float(h));
            *(unsigned short*)(sm + OFF_VH + d * AVP + r * 2) = __bfloat16_as_ushort(h);
            *(unsigned short*)(sm + OFF_VL + d * AVP + r * 2) = __bfloat16_as_ushort(l);
        }
        __syncthreads();

        // S = Q K^T  (16 x 64 per warp)
        float sfr[8][4];
        #pragma unroll
        for (int j = 0; j < 8; ++j)
            #pragma unroll
            for (int r = 0; r < 4; ++r) sfr[j][r] = 0.f;
        #pragma unroll
        for (int ks = 0; ks < 8; ++ks) {
            uint32_t qh[4], ql[4];
            const uint32_t qa = sb + OFF_QH + (wid * 16 + arow) * AQP + (ks * 2 + achunk) * 16;
            ldsm4(qh, qa);
            ldsm4(ql, qa + (OFF_QL - OFF_QH));
            #pragma unroll
            for (int j = 0; j < 8; ++j) {
                uint32_t kh2[2], kl2[2];
                const uint32_t ka = sb + OFF_KH + (8 * j + brow) * AKP + (ks * 2 + bchunk) * 16;
                ldsm2(kh2, ka);
                ldsm2(kl2, ka + (OFF_KL - OFF_KH));
                mma_bf16(sfr[j], qh, kh2);
                mma_bf16(sfr[j], qh, kl2);
                mma_bf16(sfr[j], ql, kh2);
            }
        }

        // causal mask (only tiles that can cross the diagonal)
        if (kt * 64 + 63 > rb) {
            #pragma unroll
            for (int j = 0; j < 8; ++j) {
                const int col = kt * 64 + 8 * j + 2 * qid;
                const int r0g = rb + grp, r1g = rb + grp + 8;
                if (col     > r0g) sfr[j][0] = -3.0e38f;
                if (col + 1 > r0g) sfr[j][1] = -3.0e38f;
                if (col     > r1g) sfr[j][2] = -3.0e38f;
                if (col + 1 > r1g) sfr[j][3] = -3.0e38f;
            }
        }

        // warp-local online softmax (rows grp and grp+8 of this warp's 16)
        float ml0 = -3.0e38f, ml1 = -3.0e38f;
        #pragma unroll
        for (int j = 0; j < 8; ++j) {
            ml0 = fmaxf(ml0, fmaxf(sfr[j][0], sfr[j][1]));
            ml1 = fmaxf(ml1, fmaxf(sfr[j][2], sfr[j][3]));
        }
        ml0 = fmaxf(ml0, __shfl_xor_sync(0xffffffffu, ml0, 1));
        ml0 = fmaxf(ml0, __shfl_xor_sync(0xffffffffu, ml0, 2));
        ml1 = fmaxf(ml1, __shfl_xor_sync(0xffffffffu, ml1, 1));
        ml1 = fmaxf(ml1, __shfl_xor_sync(0xffffffffu, ml1, 2));
        const float mn0 = fmaxf(m0, ml0), mn1 = fmaxf(m1, ml1);
        const float sc0 = expf(m0 - mn0), sc1 = expf(m1 - mn1);
        m0 = mn0; m1 = mn1;

        float rs0 = 0.f, rs1 = 0.f;
        uint32_t pah[4][4], pal[4][4];
        #pragma unroll
        for (int t = 0; t < 4; ++t) {
            const float p00 = expf(sfr[2*t][0] - mn0), p01 = expf(sfr[2*t][1] - mn0);
            const float p02 = expf(sfr[2*t][2] - mn1), p03 = expf(sfr[2*t][3] - mn1);
            const float p10 = expf(sfr[2*t+1][0] - mn0), p11 = expf(sfr[2*t+1][1] - mn0);
            const float p12 = expf(sfr[2*t+1][2] - mn1), p13 = expf(sfr[2*t+1][3] - mn1);
            rs0 += p00 + p01 + p10 + p11;
            rs1 += p02 + p03 + p12 + p13;
            split_pack2(p00, p01, pah[t][0], pal[t][0]);
            split_pack2(p02, p03, pah[t][1], pal[t][1]);
            split_pack2(p10, p11, pah[t][2], pal[t][2]);
            split_pack2(p12, p13, pah[t][3], pal[t][3]);
        }
        rs0 += __shfl_xor_sync(0xffffffffu, rs0, 1);
        rs0 += __shfl_xor_sync(0xffffffffu, rs0, 2);
        rs1 += __shfl_xor_sync(0xffffffffu, rs1, 1);
        rs1 += __shfl_xor_sync(0xffffffffu, rs1, 2);
        l0 = l0 * sc0 + rs0;
        l1 = l1 * sc1 + rs1;

        #pragma unroll
        for (int n = 0; n < 16; ++n) {
            of[n][0] *= sc0; of[n][1] *= sc0;
            of[n][2] *= sc1; of[n][3] *= sc1;
        }
        // O += P V   (K-dim = 64 kpos, N = 128 head dims)
        #pragma unroll
        for (int t = 0; t < 4; ++t) {
            #pragma unroll
            for (int n = 0; n < 16; ++n) {
                uint32_t vh2[2], vl2[2];
                const uint32_t va = sb + OFF_VH + (8 * n + brow) * AVP + (t * 2 + bchunk) * 16;
                ldsm2(vh2, va);
                ldsm2(vl2, va + (OFF_VL - OFF_VH));
                mma_bf16(of[n], pah[t], vh2);
                mma_bf16(of[n], pah[t], vl2);
                mma_bf16(of[n], pal[t], vh2);
            }
        }
    }

    // epilogue: normalize and split-store
    const float li0 = 1.f / l0, li1 = 1.f / l1;
    const long long row0 = (long long)(tok0 + wid * 16 + grp);
    #pragma unroll
    for (int n = 0; n < 16; ++n) {
        const long long col = hh * HDc + 8 * n + 2 * qid;
        uint32_t h2, l2;
        split_pack2(of[n][0] * li0, of[n][1] * li0, h2, l2);
        *(uint32_t*)(oh + row0 * Dc + col) = h2;
        *(uint32_t*)(ol + row0 * Dc + col) = l2;
        split_pack2(of[n][2] * li1, of[n][3] * li1, h2, l2);
        *(uint32_t*)(oh + (row0 + 8) * Dc + col) = h2;
        *(uint32_t*)(ol + (row0 + 8) * Dc + col) = l2;
    }
}

// ---------------- silu(gate)*up -> split bf16 -------------------------------
__global__ void silu_kernel(__nv_bfloat16* __restrict__ ah,
                            __nv_bfloat16* __restrict__ al,
                            const float* __restrict__ gu) {
    const long long idx = ((long long)blockIdx.x * blockDim.x + threadIdx.x) * 4;
    if (idx >= (long long)Tc * Ic) return;
    const int t = (int)(idx / Ic);
    const int i = (int)(idx - (long long)t * Ic);
    float4 g = *(const float4*)(gu + (long long)t * GUc + i);
    float4 u = *(const float4*)(gu + (long long)t * GUc + Ic + i);
    float4 a;
    a.x = (g.x / (1.f + expf(-g.x))) * u.x;
    a.y = (g.y / (1.f + expf(-g.y))) * u.y;
    a.z = (g.z / (1.f + expf(-g.z))) * u.z;
    a.w = (g.w / (1.f + expf(-g.w))) * u.w;
    split_store4(ah, al, idx, a);
}

// ---------------- launch ----------------------------------------------------
extern "C" void kernel_launch(void* const* d_in, const int* in_sizes, int n_in,
                              void* d_out, int out_size) {
    const int*   ids    = (const int*)  d_in[0];
    const int*   pos    = (const int*)  d_in[1];
    const float* embed  = (const float*)d_in[2];
    const float* Wqkv   = (const float*)d_in[3];
    const float* Wo     = (const float*)d_in[4];
    const float* Wgu    = (const float*)d_in[5];
    const float* Wd     = (const float*)d_in[6];
    const float* ln1    = (const float*)d_in[7];
    const float* ln2    = (const float*)d_in[8];
    const float* norm_w = (const float*)d_in[9];
    const float* lmh    = (const float*)d_in[10];
    float* out = (float*)d_out;

    float *h, *qkv, *gu;
    __nv_bfloat16 *xh, *xl, *oh, *ol, *ah, *al;
    __nv_bfloat16 *wqkvh, *wqkvl, *woh, *wol, *wguh, *wgul, *wdh, *wdl, *lmhh, *lmhl;
    cudaGetSymbolAddress((void**)&h,   g_h);
    cudaGetSymbolAddress((void**)&qkv, g_qkv);
    cudaGetSymbolAddress((void**)&gu,  g_gu);
    cudaGetSymbolAddress((void**)&xh,  g_xh);  cudaGetSymbolAddress((void**)&xl, g_xl);
    cudaGetSymbolAddress((void**)&oh,  g_oh);  cudaGetSymbolAddress((void**)&ol, g_ol);
    cudaGetSymbolAddress((void**)&ah,  g_ah);  cudaGetSymbolAddress((void**)&al, g_al);
    cudaGetSymbolAddress((void**)&wqkvh, g_wqkvh); cudaGetSymbolAddress((void**)&wqkvl, g_wqkvl);
    cudaGetSymbolAddress((void**)&woh,   g_woh);   cudaGetSymbolAddress((void**)&wol,   g_wol);
    cudaGetSymbolAddress((void**)&wguh,  g_wguh);  cudaGetSymbolAddress((void**)&wgul,  g_wgul);
    cudaGetSymbolAddress((void**)&wdh,   g_wdh);   cudaGetSymbolAddress((void**)&wdl,   g_wdl);
    cudaGetSymbolAddress((void**)&lmhh,  g_lmhh);  cudaGetSymbolAddress((void**)&lmhl,  g_lmhl);

    cudaFuncSetAttribute(attn_kernel,
                         cudaFuncAttributeMaxDynamicSharedMemorySize, ATTN_SMEM);
    cudaFuncSetAttribute(gemm_bf16x3,
                         cudaFuncAttributeMaxDynamicSharedMemorySize, GEMM_SMEM);

    // split all weights into bf16 hi/lo
    {
        const long long n1 = (long long)Lc*QKVc*Dc, n2 = (long long)Lc*Dc*Dc,
                        n3 = (long long)Lc*GUc*Dc,  n4 = (long long)Lc*Dc*Ic,
                        n5 = (long long)Vc*Dc;
        split_kernel<<<(unsigned)((n1/4 + 255)/256), 256>>>(Wqkv, wqkvh, wqkvl, n1);
        split_kernel<<<(unsigned)((n2/4 + 255)/256), 256>>>(Wo,   woh,   wol,   n2);
        split_kernel<<<(unsigned)((n3/4 + 255)/256), 256>>>(Wgu,  wguh,  wgul,  n3);
        split_kernel<<<(unsigned)((n4/4 + 255)/256), 256>>>(Wd,   wdh,   wdl,   n4);
        split_kernel<<<(unsigned)((n5/4 + 255)/256), 256>>>(lmh,  lmhh,  lmhl,  n5);
    }

    embed_kernel<<<Tc, 128>>>(ids, embed, h);

    for (int l = 0; l < Lc; ++l) {
        rmsnorm_kernel<<<Tc, 256>>>(xh, xl, h, ln1 + (long long)l * Dc);
        gemm_bf16x3<<<dim3(Tc/128, QKVc/128), 256, GEMM_SMEM>>>(
            xh, xl, wqkvh + (long long)l*QKVc*Dc, wqkvl + (long long)l*QKVc*Dc,
            qkv, Tc, QKVc, Dc, 0);
        rope_kernel<<<(Tc * Hc * 64 + 255) / 256, 256>>>(qkv, pos);
        attn_kernel<<<dim3(Sc / 128, Hc, Bc), 256, ATTN_SMEM>>>(qkv, oh, ol);
        gemm_bf16x3<<<dim3(Tc/128, Dc/128), 256, GEMM_SMEM>>>(
            oh, ol, woh + (long long)l*Dc*Dc, wol + (long long)l*Dc*Dc,
            h, Tc, Dc, Dc, 1);
        rmsnorm_kernel<<<Tc, 256>>>(xh, xl, h, ln2 + (long long)l * Dc);
        gemm_bf16x3<<<dim3(Tc/128, GUc/128), 256, GEMM_SMEM>>>(
            xh, xl, wguh + (long long)l*GUc*Dc, wgul + (long long)l*GUc*Dc,
            gu, Tc, GUc, Dc, 0);
        silu_kernel<<<(unsigned)(((long long)Tc*Ic/4 + 255)/256), 256>>>(ah, al, gu);
        gemm_bf16x3<<<dim3(Tc/128, Dc/128), 256, GEMM_SMEM>>>(
            ah, al, wdh + (long long)l*Dc*Ic, wdl + (long long)l*Dc*Ic,
            h, Tc, Dc, Ic, 1);
    }

    rmsnorm_kernel<<<Tc, 256>>>(xh, xl, h, norm_w);
    gemm_bf16x3<<<dim3(Tc/128, Vc/128), 256, GEMM_SMEM>>>(
        xh, xl, lmhh, lmhl, out, Tc, Vc, Dc, 0);
}